// round 1
// baseline (speedup 1.0000x reference)
#include <cuda_runtime.h>

#define BB   16
#define NN   128
#define FIN  8
#define SDIM 8
#define FO   64
#define KH   32

// Scratch (allocation-free rule: device globals)
__device__ float g_w2x[BB * NN * KH * FO];   // [b,i,k,o]  16.8 MB
__device__ float g_bt [BB * NN * FO];        // [b,i,o]
__device__ float g_act[BB * NN * FO];        // [b,n,o] post-ReLU activations

// ---------------------------------------------------------------------------
// k1: W2x[b,i,k,o] = sum_f kn_w2[k, f*FO+o] * X[b,i,f];  bt[b,i,o] = sum_f kn_b2[f*FO+o]*X[b,i,f]
// grid = B*N blocks, 64 threads (one per o). kn_w2 (64KB) is L1/L2 resident.
// ---------------------------------------------------------------------------
__global__ void k1_w2x(const float* __restrict__ X,
                       const float* __restrict__ kn_w2,
                       const float* __restrict__ kn_b2) {
    int bi = blockIdx.x;           // b*N + i
    int o  = threadIdx.x;          // 0..63
    float xv[FIN];
    const float* x = X + bi * FIN;
#pragma unroll
    for (int f = 0; f < FIN; ++f) xv[f] = x[f];

    float* w2xout = g_w2x + (size_t)bi * KH * FO + o;
#pragma unroll 4
    for (int k = 0; k < KH; ++k) {
        float s = 0.f;
        const float* w2 = kn_w2 + k * (FIN * FO) + o;
#pragma unroll
        for (int f = 0; f < FIN; ++f) s = fmaf(w2[f * FO], xv[f], s);
        w2xout[k * FO] = s;
    }
    float bt = 0.f;
#pragma unroll
    for (int f = 0; f < FIN; ++f) bt = fmaf(kn_b2[f * FO + o], xv[f], bt);
    g_bt[bi * FO + o] = bt;
}

// ---------------------------------------------------------------------------
// k2: per (b,n): out[o] = sum_{i in nnz(A[b,n,:])} A[b,n,i] * ( sum_k h_k * W2x[b,i,k,o] + bt[b,i,o] )
//     + root term, ReLU, store to g_act.
// grid = B*N blocks, 64 threads (one per o). Warp0 computes the edge MLP h.
// ---------------------------------------------------------------------------
__global__ void k2_conv(const float* __restrict__ A,
                        const float* __restrict__ X,
                        const float* __restrict__ E,
                        const float* __restrict__ kn_w1,
                        const float* __restrict__ kn_b1,
                        const float* __restrict__ root_w,
                        const float* __restrict__ conv_b) {
    int bn = blockIdx.x;           // b*N + n
    int b  = bn >> 7;
    int o  = threadIdx.x;          // 0..63

    __shared__ float sA[NN];
    __shared__ float sh[KH];
    __shared__ float sw1[SDIM * KH];
    __shared__ float sb1[KH];
    __shared__ int   snz[NN];
    __shared__ int   scnt;

    sA[o]      = A[bn * NN + o];
    sA[o + 64] = A[bn * NN + o + 64];
    if (o < KH) sb1[o] = kn_b1[o];
    for (int t = o; t < SDIM * KH; t += 64) sw1[t] = kn_w1[t];
    __syncthreads();

    if (o == 0) {
        int c = 0;
        for (int i = 0; i < NN; ++i)
            if (sA[i] != 0.f) snz[c++] = i;
        scnt = c;
    }
    __syncthreads();
    int cnt = scnt;

    float acc = 0.f;
    for (int j = 0; j < cnt; ++j) {
        int i = snz[j];
        // warp 0: edge MLP h = relu(E[b,n,i,:] @ kn_w1 + kn_b1)
        if (o < KH) {
            const float* e = E + ((size_t)bn * NN + i) * SDIM;
            float hv = sb1[o];
#pragma unroll
            for (int s = 0; s < SDIM; ++s) hv = fmaf(e[s], sw1[s * KH + o], hv);
            sh[o] = fmaxf(hv, 0.f);
        }
        __syncthreads();

        float a   = sA[i];
        float dot = g_bt[(b * NN + i) * FO + o];
        const float* w = g_w2x + ((size_t)(b * NN + i) * KH) * FO + o;
#pragma unroll
        for (int k = 0; k < KH; ++k) dot = fmaf(sh[k], w[k * FO], dot);
        acc = fmaf(a, dot, acc);
        __syncthreads();    // protect sh before next overwrite
    }

    // root weight + bias + ReLU
    float rt = conv_b[o];
    const float* xr = X + bn * FIN;
#pragma unroll
    for (int f = 0; f < FIN; ++f) rt = fmaf(xr[f], root_w[f * FO + o], rt);
    g_act[bn * FO + o] = fmaxf(acc + rt, 0.f);
}

// ---------------------------------------------------------------------------
// k3: pool over n, Dense(32, relu), Dense(1, sigmoid). grid = B blocks, 64 threads.
// ---------------------------------------------------------------------------
__global__ void k3_head(const float* __restrict__ fc_w,
                        const float* __restrict__ fc_b,
                        const float* __restrict__ out_w,
                        const float* __restrict__ out_b,
                        float* __restrict__ out) {
    int b = blockIdx.x;
    int t = threadIdx.x;           // 0..63
    __shared__ float sp[FO];

    float s = 0.f;
    const float* a = g_act + (size_t)b * NN * FO + t;
    for (int n = 0; n < NN; ++n) s += a[n * FO];
    sp[t] = s * (1.f / NN);
    __syncthreads();

    if (t < 32) {
        float f = fc_b[t];
#pragma unroll
        for (int o2 = 0; o2 < FO; ++o2) f = fmaf(sp[o2], fc_w[o2 * 32 + t], f);
        f = fmaxf(f, 0.f);
        float p = f * out_w[t];
#pragma unroll
        for (int off = 16; off > 0; off >>= 1)
            p += __shfl_xor_sync(0xffffffffu, p, off);
        if (t == 0) out[b] = 1.f / (1.f + expf(-(p + out_b[0])));
    }
}

// ---------------------------------------------------------------------------
// Inputs (metadata order): A, X, E, kn_w1, kn_b1, kn_w2, kn_b2, root_w, conv_b,
//                          fc_w, fc_b, out_w, out_b
// ---------------------------------------------------------------------------
extern "C" void kernel_launch(void* const* d_in, const int* in_sizes, int n_in,
                              void* d_out, int out_size) {
    const float* A      = (const float*)d_in[0];
    const float* X      = (const float*)d_in[1];
    const float* E      = (const float*)d_in[2];
    const float* kn_w1  = (const float*)d_in[3];
    const float* kn_b1  = (const float*)d_in[4];
    const float* kn_w2  = (const float*)d_in[5];
    const float* kn_b2  = (const float*)d_in[6];
    const float* root_w = (const float*)d_in[7];
    const float* conv_b = (const float*)d_in[8];
    const float* fc_w   = (const float*)d_in[9];
    const float* fc_b   = (const float*)d_in[10];
    const float* out_w  = (const float*)d_in[11];
    const float* out_b  = (const float*)d_in[12];
    float* out = (float*)d_out;

    k1_w2x <<<BB * NN, 64>>>(X, kn_w2, kn_b2);
    k2_conv<<<BB * NN, 64>>>(A, X, E, kn_w1, kn_b1, root_w, conv_b);
    k3_head<<<BB, 64>>>(fc_w, fc_b, out_w, out_b, out);
}

// round 2
// speedup vs baseline: 2.0256x; 2.0256x over previous
#include <cuda_runtime.h>

#define BB   16
#define NN   128
#define FIN  8
#define SDIM 8
#define FO   64
#define KH   32

// Accumulator for conv output (pre-ReLU). Device global (allocation-free rule).
__device__ float g_act[BB * NN * FO];        // [b,n,o]

// ---------------------------------------------------------------------------
// k0: g_act[b,n,o] = X[b,n,:] @ root_w[:,o] + conv_b[o]   (overwrite each call)
// grid = B*N, 64 threads.
// ---------------------------------------------------------------------------
__global__ void k0_init(const float* __restrict__ X,
                        const float* __restrict__ root_w,
                        const float* __restrict__ conv_b) {
    int bn = blockIdx.x;
    int o  = threadIdx.x;
    const float* x = X + bn * FIN;
    float rt = conv_b[o];
#pragma unroll
    for (int f = 0; f < FIN; ++f) rt = fmaf(x[f], root_w[f * FO + o], rt);
    g_act[bn * FO + o] = rt;
}

// ---------------------------------------------------------------------------
// k_scatter: block = (b,i) source node. W2x[k][o] lives in registers of thread o.
// For each n with A[b,n,i] != 0: h = relu(E[b,n,i,:]@w1+b1), then
// atomicAdd(g_act[b,n,o], A * (sum_k h_k * W2x[k][o] + bt[o])).
// grid = B*N, 64 threads.
// ---------------------------------------------------------------------------
__global__ void k_scatter(const float* __restrict__ A,
                          const float* __restrict__ X,
                          const float* __restrict__ E,
                          const float* __restrict__ kn_w1,
                          const float* __restrict__ kn_b1,
                          const float* __restrict__ kn_w2,
                          const float* __restrict__ kn_b2) {
    int bi = blockIdx.x;               // b*N + i
    int b  = bi >> 7;
    int i  = bi & 127;
    int t  = threadIdx.x;              // 0..63  (= o in dot phase)

    __shared__ float sw1[SDIM * KH];   // kn_w1 [s][k]
    __shared__ float sb1[KH];
    __shared__ float sh[NN * KH];      // h per edge (cap NN edges) 16KB
    __shared__ float sa[NN];           // A values per edge
    __shared__ int   sn[NN];           // n index per edge
    __shared__ int   scnt;

    // --- load edge-MLP layer-1 weights; find nnz of column A[b,:,i] ---
    for (int u = t; u < SDIM * KH; u += 64) sw1[u] = kn_w1[u];
    if (t < KH) sb1[t] = kn_b1[t];
    if (t == 0) scnt = 0;
    __syncthreads();

    const float* Ab = A + (size_t)b * NN * NN + i;   // A[b, n, i], stride NN
#pragma unroll
    for (int r = 0; r < 2; ++r) {
        int n = t + r * 64;
        float a = Ab[n * NN];
        if (a != 0.f) {
            int j = atomicAdd(&scnt, 1);
            sa[j] = a;
            sn[j] = n;
        }
    }
    __syncthreads();
    int cnt = scnt;
    if (cnt == 0) return;

    // --- W2x[k][o=t] in registers; bt[o=t] ---
    float xv[FIN];
    const float* x = X + bi * FIN;
#pragma unroll
    for (int f = 0; f < FIN; ++f) xv[f] = x[f];

    float w2x[KH];
#pragma unroll
    for (int k = 0; k < KH; ++k) {
        float s = 0.f;
        const float* w2 = kn_w2 + k * (FIN * FO) + t;
#pragma unroll
        for (int f = 0; f < FIN; ++f) s = fmaf(w2[f * FO], xv[f], s);
        w2x[k] = s;
    }
    float bt = 0.f;
#pragma unroll
    for (int f = 0; f < FIN; ++f) bt = fmaf(kn_b2[f * FO + t], xv[f], bt);

    // --- edge MLP layer 1 for all edges: work item = (edge j, hidden k) ---
    for (int u = t; u < cnt * KH; u += 64) {
        int j = u >> 5;                // edge
        int k = u & 31;                // hidden unit
        const float* e = E + (((size_t)b * NN + sn[j]) * NN + i) * SDIM;
        float hv = sb1[k];
#pragma unroll
        for (int s = 0; s < SDIM; ++s) hv = fmaf(e[s], sw1[s * KH + k], hv);
        sh[u] = fmaxf(hv, 0.f);
    }
    __syncthreads();

    // --- dot + scatter: thread t = output channel o ---
    for (int j = 0; j < cnt; ++j) {
        const float* hj = sh + j * KH;
        float dot = bt;
#pragma unroll
        for (int k = 0; k < KH; ++k) dot = fmaf(hj[k], w2x[k], dot);
        atomicAdd(&g_act[((size_t)b * NN + sn[j]) * FO + t], sa[j] * dot);
    }
}

// ---------------------------------------------------------------------------
// k_head: ReLU + mean over n, Dense(32, relu), Dense(1, sigmoid).
// grid = B, 64 threads.
// ---------------------------------------------------------------------------
__global__ void k_head(const float* __restrict__ fc_w,
                       const float* __restrict__ fc_b,
                       const float* __restrict__ out_w,
                       const float* __restrict__ out_b,
                       float* __restrict__ out) {
    int b = blockIdx.x;
    int t = threadIdx.x;
    __shared__ float sp[FO];

    float s = 0.f;
    const float* a = g_act + (size_t)b * NN * FO + t;
    for (int n = 0; n < NN; ++n) s += fmaxf(a[n * FO], 0.f);
    sp[t] = s * (1.f / NN);
    __syncthreads();

    if (t < 32) {
        float f = fc_b[t];
#pragma unroll
        for (int o2 = 0; o2 < FO; ++o2) f = fmaf(sp[o2], fc_w[o2 * 32 + t], f);
        f = fmaxf(f, 0.f);
        float p = f * out_w[t];
#pragma unroll
        for (int off = 16; off > 0; off >>= 1)
            p += __shfl_xor_sync(0xffffffffu, p, off);
        if (t == 0) out[b] = 1.f / (1.f + expf(-(p + out_b[0])));
    }
}

// ---------------------------------------------------------------------------
// Inputs (metadata order): A, X, E, kn_w1, kn_b1, kn_w2, kn_b2, root_w, conv_b,
//                          fc_w, fc_b, out_w, out_b
// ---------------------------------------------------------------------------
extern "C" void kernel_launch(void* const* d_in, const int* in_sizes, int n_in,
                              void* d_out, int out_size) {
    const float* A      = (const float*)d_in[0];
    const float* X      = (const float*)d_in[1];
    const float* E      = (const float*)d_in[2];
    const float* kn_w1  = (const float*)d_in[3];
    const float* kn_b1  = (const float*)d_in[4];
    const float* kn_w2  = (const float*)d_in[5];
    const float* kn_b2  = (const float*)d_in[6];
    const float* root_w = (const float*)d_in[7];
    const float* conv_b = (const float*)d_in[8];
    const float* fc_w   = (const float*)d_in[9];
    const float* fc_b   = (const float*)d_in[10];
    const float* out_w  = (const float*)d_in[11];
    const float* out_b  = (const float*)d_in[12];
    float* out = (float*)d_out;

    k0_init  <<<BB * NN, 64>>>(X, root_w, conv_b);
    k_scatter<<<BB * NN, 64>>>(A, X, E, kn_w1, kn_b1, kn_w2, kn_b2);
    k_head   <<<BB, 64>>>(fc_w, fc_b, out_w, out_b, out);
}

// round 3
// speedup vs baseline: 2.5159x; 1.2420x over previous
#include <cuda_runtime.h>

#define BB    16
#define NN    128
#define FIN   8
#define SDIM  8
#define FO    64
#define KH    32
#define CHUNK 32

// Edge-contribution accumulator. .bss => zero at context init; k_head restores
// zeros after reading, so every call (and every graph replay) starts from zero.
__device__ float g_act[BB * NN * FO];        // [b,n,o]

// ---------------------------------------------------------------------------
// k_scatter: block = (b,i) source node, 64 threads (t = output channel o).
// W2x[k][o] computed with float4 kn_w2 loads via smem handoff into registers.
// For each n with A[b,n,i] != 0: h = relu(E[b,n,i,:]@w1+b1), then
// atomicAdd(g_act[b,n,o], A * (sum_k h_k * w2x[k] + bt)).
// ---------------------------------------------------------------------------
__global__ void k_scatter(const float* __restrict__ A,
                          const float* __restrict__ X,
                          const float* __restrict__ E,
                          const float* __restrict__ kn_w1,
                          const float* __restrict__ kn_b1,
                          const float* __restrict__ kn_w2,
                          const float* __restrict__ kn_b2) {
    int bi = blockIdx.x;               // b*N + i
    int b  = bi >> 7;
    int i  = bi & 127;
    int t  = threadIdx.x;              // 0..63

    __shared__ float sw1[SDIM * KH];   // 1KB   kn_w1 [s][k]
    __shared__ float sb1[KH];
    __shared__ float sw2x[KH * FO];    // 8KB   w2x[k][o] handoff
    __shared__ float sh[CHUNK * KH];   // 4KB   h per edge chunk
    __shared__ float sa[NN];
    __shared__ int   sn[NN];
    __shared__ int   scnt;

    for (int u = t; u < SDIM * KH; u += 64) sw1[u] = kn_w1[u];
    if (t < KH) sb1[t] = kn_b1[t];
    if (t == 0) scnt = 0;
    __syncthreads();

    // nnz of A[b, :, i] (column, strided)
    const float* Ab = A + (size_t)b * NN * NN + i;
#pragma unroll
    for (int r = 0; r < 2; ++r) {
        int n = t + r * 64;
        float a = Ab[n * NN];
        if (a != 0.f) {
            int j = atomicAdd(&scnt, 1);
            sa[j] = a;
            sn[j] = n;
        }
    }

    // xv = X[b,i,:]
    float xv[FIN];
    const float* x = X + bi * FIN;
#pragma unroll
    for (int f = 0; f < FIN; ++f) xv[f] = x[f];

    // W2x[k][o] = sum_f kn_w2[k, f*FO+o] * xv[f], computed as float4 o-quads.
    // item idx = t + 64*it : k = idx>>4 (0..31), q = idx&15 (o-quad 0..15)
    const float4* W4 = (const float4*)kn_w2;   // float4 idx = k*128 + f*16 + q
#pragma unroll
    for (int it = 0; it < 8; ++it) {
        int idx = t + 64 * it;
        int k = idx >> 4, q = idx & 15;
        float4 acc = make_float4(0.f, 0.f, 0.f, 0.f);
#pragma unroll
        for (int f = 0; f < FIN; ++f) {
            float4 w = W4[k * 128 + f * 16 + q];
            acc.x = fmaf(w.x, xv[f], acc.x);
            acc.y = fmaf(w.y, xv[f], acc.y);
            acc.z = fmaf(w.z, xv[f], acc.z);
            acc.w = fmaf(w.w, xv[f], acc.w);
        }
        ((float4*)sw2x)[k * 16 + q] = acc;
    }

    // bt[o=t] = sum_f kn_b2[f*FO+o] * xv[f]
    float bt = 0.f;
#pragma unroll
    for (int f = 0; f < FIN; ++f) bt = fmaf(kn_b2[f * FO + t], xv[f], bt);

    __syncthreads();
    int cnt = scnt;
    if (cnt == 0) return;

    float w2x[KH];
#pragma unroll
    for (int k = 0; k < KH; ++k) w2x[k] = sw2x[k * FO + t];

    for (int j0 = 0; j0 < cnt; j0 += CHUNK) {
        int m = cnt - j0; if (m > CHUNK) m = CHUNK;

        // h = relu(E@w1 + b1) for edges [j0, j0+m); work item = (edge, k)
        for (int u = t; u < m * KH; u += 64) {
            int j = u >> 5;
            int k = u & 31;
            const float4* e4 = (const float4*)(E + (((size_t)b * NN + sn[j0 + j]) * NN + i) * SDIM);
            float4 e0 = e4[0], e1 = e4[1];
            float hv = sb1[k];
            hv = fmaf(e0.x, sw1[0 * KH + k], hv);
            hv = fmaf(e0.y, sw1[1 * KH + k], hv);
            hv = fmaf(e0.z, sw1[2 * KH + k], hv);
            hv = fmaf(e0.w, sw1[3 * KH + k], hv);
            hv = fmaf(e1.x, sw1[4 * KH + k], hv);
            hv = fmaf(e1.y, sw1[5 * KH + k], hv);
            hv = fmaf(e1.z, sw1[6 * KH + k], hv);
            hv = fmaf(e1.w, sw1[7 * KH + k], hv);
            sh[u] = fmaxf(hv, 0.f);
        }
        __syncthreads();

        for (int j = 0; j < m; ++j) {
            const float* hj = sh + j * KH;
            float dot = bt;
#pragma unroll
            for (int k = 0; k < KH; ++k) dot = fmaf(hj[k], w2x[k], dot);
            atomicAdd(&g_act[((size_t)b * NN + sn[j0 + j]) * FO + t], sa[j0 + j] * dot);
        }
        __syncthreads();
    }
}

// ---------------------------------------------------------------------------
// k_head: per b: for each n, acc = g_act[b,n,o] (then restore 0), add root
// term + bias, ReLU, pool over n; Dense(32,relu); Dense(1,sigmoid).
// grid = B, 256 threads: o = t&63, quarter = t>>6 handles 32 n's.
// ---------------------------------------------------------------------------
__global__ void k_head(const float* __restrict__ X,
                       const float* __restrict__ root_w,
                       const float* __restrict__ conv_b,
                       const float* __restrict__ fc_w,
                       const float* __restrict__ fc_b,
                       const float* __restrict__ out_w,
                       const float* __restrict__ out_b,
                       float* __restrict__ out) {
    int b = blockIdx.x;
    int t = threadIdx.x;               // 0..255
    int o = t & 63;
    int qt = t >> 6;                   // 0..3

    __shared__ float sX[NN * FIN];     // 4KB  X[b]
    __shared__ float srw[FIN * FO];    // 2KB  root_w
    __shared__ float sp[256];
    __shared__ float sfeat[FO];

    for (int u = t; u < NN * FIN / 4; u += 256)
        ((float4*)sX)[u] = ((const float4*)(X + (size_t)b * NN * FIN))[u];
    for (int u = t; u < FIN * FO / 4; u += 256)
        ((float4*)srw)[u] = ((const float4*)root_w)[u];
    __syncthreads();

    float rw[FIN];
#pragma unroll
    for (int f = 0; f < FIN; ++f) rw[f] = srw[f * FO + o];
    float cb = conv_b[o];

    float s = 0.f;
    float* ga = g_act + ((size_t)b * NN + qt * 32) * FO + o;
    const float* xr0 = sX + (qt * 32) * FIN;
#pragma unroll 4
    for (int n = 0; n < 32; ++n) {
        float acc = ga[n * FO];
        ga[n * FO] = 0.f;              // restore zero for next call/replay
        const float* xr = xr0 + n * FIN;
        float rt = cb;
#pragma unroll
        for (int f = 0; f < FIN; ++f) rt = fmaf(xr[f], rw[f], rt);
        s += fmaxf(acc + rt, 0.f);
    }
    sp[t] = s;
    __syncthreads();

    if (t < FO)
        sfeat[t] = (sp[t] + sp[t + 64] + sp[t + 128] + sp[t + 192]) * (1.f / NN);
    __syncthreads();

    if (t < 32) {
        float f = fc_b[t];
#pragma unroll
        for (int o2 = 0; o2 < FO; ++o2) f = fmaf(sfeat[o2], fc_w[o2 * 32 + t], f);
        f = fmaxf(f, 0.f);
        float p = f * out_w[t];
#pragma unroll
        for (int off = 16; off > 0; off >>= 1)
            p += __shfl_xor_sync(0xffffffffu, p, off);
        if (t == 0) out[b] = 1.f / (1.f + expf(-(p + out_b[0])));
    }
}

// ---------------------------------------------------------------------------
// Inputs (metadata order): A, X, E, kn_w1, kn_b1, kn_w2, kn_b2, root_w, conv_b,
//                          fc_w, fc_b, out_w, out_b
// ---------------------------------------------------------------------------
extern "C" void kernel_launch(void* const* d_in, const int* in_sizes, int n_in,
                              void* d_out, int out_size) {
    const float* A      = (const float*)d_in[0];
    const float* X      = (const float*)d_in[1];
    const float* E      = (const float*)d_in[2];
    const float* kn_w1  = (const float*)d_in[3];
    const float* kn_b1  = (const float*)d_in[4];
    const float* kn_w2  = (const float*)d_in[5];
    const float* kn_b2  = (const float*)d_in[6];
    const float* root_w = (const float*)d_in[7];
    const float* conv_b = (const float*)d_in[8];
    const float* fc_w   = (const float*)d_in[9];
    const float* fc_b   = (const float*)d_in[10];
    const float* out_w  = (const float*)d_in[11];
    const float* out_b  = (const float*)d_in[12];
    float* out = (float*)d_out;

    k_scatter<<<BB * NN, 64>>>(A, X, E, kn_w1, kn_b1, kn_w2, kn_b2);
    k_head   <<<BB, 256>>>(X, root_w, conv_b, fc_w, fc_b, out_w, out_b, out);
}